// round 5
// baseline (speedup 1.0000x reference)
#include <cuda_runtime.h>
#include <cstdint>
#include <cstddef>

// Problem constants
#define BATCH 8
#define TSEQ  1024
#define DDIM  384
#define DLANG 768
#define HID   512

#define NB       128      // total blocks (<= 148 SMs -> all co-resident)
#define CHAIN_NB 32       // blocks 0..31 run the GEMV chain
#define NTHR     256

// Scratch + barrier state (allocation-free rule: __device__ globals)
__device__ float g_buf0[BATCH * HID];
__device__ float g_buf1[BATCH * HID];
__device__ float g_f[BATCH * DDIM];
__device__ unsigned g_barrier[8];   // zeroed each launch via captured cudaMemsetAsync

// Dynamic smem layout:
//   float4 tile[6144]       : 98304 B  (state tile: 64 rows x 96 float4)
//   float  sinT[3072]       : 12288 B  (4 input vectors interleaved [K][4]; reused for f)
//   float  spart[1024]      :  4096 B  (8 kslices x 4 batches x 32 cols)
//   uint64 mbar             :    16 B
#define TILE_F4    6144
#define SMEM_BYTES (TILE_F4 * 16 + 3072 * 4 + 1024 * 4 + 16)

extern __shared__ float4 smem_dyn[];

__device__ __forceinline__ uint32_t smem_u32(const void* p) {
    return (uint32_t)__cvta_generic_to_shared(p);
}

// ---------------------------------------------------------------------------
// Chain barrier among CHAIN_NB blocks (monotonic counters, memset-reset).
// ---------------------------------------------------------------------------
__device__ __forceinline__ void chain_barrier(int phase) {
    __syncthreads();
    if (threadIdx.x == 0) {
        __threadfence();
        atomicAdd(&g_barrier[phase], 1u);
        volatile unsigned* p = &g_barrier[phase];
        while (*p < CHAIN_NB) { __nanosleep(20); }
        __threadfence();
    }
    __syncthreads();
}

// ---------------------------------------------------------------------------
// One GEMV chain stage on <= CHAIN_NB blocks.
// Task = (group of 4 batches) x (jtile of 32 cols). NTASK = 2 * JT.
// out[b, j] = sum_i in[b,i] * W[i*N + j] + bias[j]
// ---------------------------------------------------------------------------
template <int K, int N, int JT>
__device__ __forceinline__ void chain_stage(const float* __restrict__ in,
                                            const float* __restrict__ W,
                                            const float* __restrict__ bias,
                                            float* __restrict__ out,
                                            float* sinT, float* spart) {
    constexpr int NTASK = 2 * JT;
    if (blockIdx.x < NTASK) {
        const int group = blockIdx.x / JT;        // 0..1 (4 batches each)
        const int jt    = blockIdx.x % JT;

        // Interleave 4 input vectors: sinT[i*4 + b] = in[group*4+b][i]
#pragma unroll
        for (int b = 0; b < 4; ++b) {
            const float* inb = in + (size_t)(group * 4 + b) * K;
            for (int i = threadIdx.x; i < K; i += NTHR)
                sinT[i * 4 + b] = inb[i];
        }
        __syncthreads();

        const int ks = threadIdx.x >> 5;          // 0..7 k-slice
        const int jj = threadIdx.x & 31;
        const int j  = jt * 32 + jj;
        constexpr int KS = K / 8;

        const float* Wp = W + (size_t)(ks * KS) * N + j;
        const float4* sp = (const float4*)(sinT + ks * KS * 4);
        float a0 = 0.f, a1 = 0.f, a2 = 0.f, a3 = 0.f;
#pragma unroll 8
        for (int i = 0; i < KS; ++i) {
            float w = Wp[(size_t)i * N];
            float4 s = sp[i];
            a0 += s.x * w; a1 += s.y * w; a2 += s.z * w; a3 += s.w * w;
        }
        spart[ks * 128 +       jj] = a0;
        spart[ks * 128 +  32 + jj] = a1;
        spart[ks * 128 +  64 + jj] = a2;
        spart[ks * 128 +  96 + jj] = a3;
        __syncthreads();

        if (threadIdx.x < 128) {
            const int b4 = threadIdx.x >> 5;
            const int jl = threadIdx.x & 31;
            float s = bias[jt * 32 + jl];
#pragma unroll
            for (int k = 0; k < 8; ++k) s += spart[k * 128 + b4 * 32 + jl];
            out[(size_t)(group * 4 + b4) * N + jt * 32 + jl] = s;
        }
    }
    // sinT reuse protected by the chain_barrier's __syncthreads.
}

// ---------------------------------------------------------------------------
// Fused kernel.
//
// Math note: language is broadcast along T, so k/v are identical for all key
// positions; softmax over a constant row is exactly uniform 1/T and ctx == v.
// The Q path and the T x T attention cancel analytically:
//   f[b] = (((language[b] Wv + bv) Wv2 + bv2) Wo + bo) Wout + bout
//   out[b,t,:] = state[b,t,:] + f[b,:]
//
// Overlap structure:
//   - each block issues ONE cp.async.bulk (TMA pipe, does NOT pollute the
//     per-SM L1 LDG FIFO) for its 96KB state tile at entry
//   - 32 blocks run the 4-stage GEMV chain with 3 internal barriers
//   - everyone waits on the final flag + their TMA mbarrier, then add+store
// ---------------------------------------------------------------------------
__global__ void __launch_bounds__(NTHR, 1)
fused_cma_kernel(const float* __restrict__ state,
                 const float* __restrict__ language,
                 const float* __restrict__ Wv,  const float* __restrict__ bv,
                 const float* __restrict__ Wv2, const float* __restrict__ bv2,
                 const float* __restrict__ Wo,  const float* __restrict__ bo,
                 const float* __restrict__ Wout,const float* __restrict__ bout,
                 float* __restrict__ out) {
    float4*   tile  = smem_dyn;                          // 6144 float4
    float*    sinT  = (float*)(smem_dyn + TILE_F4);      // 3072 floats
    float*    spart = sinT + 3072;                       // 1024 floats
    uint64_t* mbar  = (uint64_t*)(spart + 1024);

    // ---- Issue the state-tile bulk copy (TMA pipe) ----
    const int bres = blockIdx.x >> 4;                    // batch
    const int t0   = (blockIdx.x & 15) * 64;             // row start
    const size_t base = ((size_t)bres * TSEQ + t0) * DDIM;

    const uint32_t mbar_s = smem_u32(mbar);
    const uint32_t tile_s = smem_u32(tile);
    if (threadIdx.x == 0) {
        asm volatile("mbarrier.init.shared.b64 [%0], 1;" :: "r"(mbar_s) : "memory");
        asm volatile("fence.proxy.async.shared::cta;" ::: "memory");
        asm volatile("mbarrier.arrive.expect_tx.shared.b64 _, [%0], %1;"
                     :: "r"(mbar_s), "r"((unsigned)(TILE_F4 * 16)) : "memory");
        asm volatile(
            "cp.async.bulk.shared::cta.global.mbarrier::complete_tx::bytes "
            "[%0], [%1], %2, [%3];"
            :: "r"(tile_s), "l"(state + base), "r"((unsigned)(TILE_F4 * 16)),
               "r"(mbar_s) : "memory");
    }

    // ---- GEMV chain on blocks 0..CHAIN_NB-1 ----
    if (blockIdx.x < CHAIN_NB) {
        chain_stage<DLANG, HID, 16>(language, Wv,   bv,   g_buf0, sinT, spart);
        chain_barrier(0);
        chain_stage<HID,   HID, 16>(g_buf0,   Wv2,  bv2,  g_buf1, sinT, spart);
        chain_barrier(1);
        chain_stage<HID,   HID, 16>(g_buf1,   Wo,   bo,   g_buf0, sinT, spart);
        chain_barrier(2);
        chain_stage<HID,  DDIM, 12>(g_buf0,   Wout, bout, g_f,    sinT, spart);
        __syncthreads();
        if (threadIdx.x == 0) {
            __threadfence();
            atomicAdd(&g_barrier[3], 1u);       // final flag
        }
    }

    // ---- Wait for f (all blocks) ----
    if (threadIdx.x == 0) {
        volatile unsigned* p = &g_barrier[3];
        while (*p < CHAIN_NB) { __nanosleep(40); }
        __threadfence();
    }
    __syncthreads();

    // f row into smem (reuse sinT region)
    float4* fsh = (float4*)sinT;
    if (threadIdx.x < DDIM / 4) {
        fsh[threadIdx.x] =
            ((const float4*)(g_f + (size_t)bres * DDIM))[threadIdx.x];
    }
    __syncthreads();

    // ---- Wait for the state tile (mbarrier parity 0, acquire) ----
    {
        uint32_t done;
        asm volatile(
            "{\n\t.reg .pred p;\n\t"
            "mbarrier.try_wait.parity.acquire.cta.shared::cta.b64 p, [%1], 0;\n\t"
            "selp.b32 %0, 1, 0, p;\n\t}"
            : "=r"(done) : "r"(mbar_s) : "memory");
        if (!done) {
            asm volatile(
                "{\n\t.reg .pred P1;\n\t"
                "WL_%=:\n\t"
                "mbarrier.try_wait.parity.acquire.cta.shared::cta.b64 P1, [%0], 0, 0x989680;\n\t"
                "@P1 bra.uni WD_%=;\n\t"
                "bra.uni WL_%=;\n\t"
                "WD_%=:\n\t}"
                :: "r"(mbar_s) : "memory");
        }
    }

    // ---- Residual add + store: 64 rows x 96 float4 = 6144 float4 ----
    float4* op = (float4*)(out + base);
    int dq = threadIdx.x % (DDIM / 4);                   // 256 ≡ 64 (mod 96)
#pragma unroll
    for (int it = 0; it < 24; ++it) {
        const int p = threadIdx.x + it * NTHR;
        float4 s  = tile[p];
        float4 fv = fsh[dq];
        s.x += fv.x; s.y += fv.y; s.z += fv.z; s.w += fv.w;
        op[p] = s;
        dq += 64; if (dq >= DDIM / 4) dq -= DDIM / 4;
    }
}

// ---------------------------------------------------------------------------
// Inputs (metadata order):
//  0 state [B,T,D]   1 language [B,DL]
//  2 Wq 3 bq 4 Wk 5 bk 6 Wv 7 bv
//  8 Wq2 9 bq2 10 Wk2 11 bk2 12 Wv2 13 bv2
// 14 Wo 15 bo 16 Wout 17 bout
// Output: float32 [B,T,D]
// ---------------------------------------------------------------------------
extern "C" void kernel_launch(void* const* d_in, const int* in_sizes, int n_in,
                              void* d_out, int out_size) {
    (void)in_sizes; (void)n_in; (void)out_size;

    const float* state    = (const float*)d_in[0];
    const float* language = (const float*)d_in[1];
    const float* Wv   = (const float*)d_in[6];
    const float* bv   = (const float*)d_in[7];
    const float* Wv2  = (const float*)d_in[12];
    const float* bv2  = (const float*)d_in[13];
    const float* Wo   = (const float*)d_in[14];
    const float* bo   = (const float*)d_in[15];
    const float* Wout = (const float*)d_in[16];
    const float* bout = (const float*)d_in[17];
    float* out = (float*)d_out;

    cudaFuncSetAttribute(fused_cma_kernel,
                         cudaFuncAttributeMaxDynamicSharedMemorySize,
                         SMEM_BYTES);

    unsigned* barp = nullptr;
    cudaGetSymbolAddress((void**)&barp, g_barrier);

    // Reset barrier counters each launch (async memset is graph-capturable).
    cudaMemsetAsync(barp, 0, sizeof(g_barrier));

    fused_cma_kernel<<<NB, NTHR, SMEM_BYTES>>>(state, language,
                                               Wv, bv, Wv2, bv2, Wo, bo,
                                               Wout, bout, out);
}

// round 7
// speedup vs baseline: 1.6688x; 1.6688x over previous
#include <cuda_runtime.h>
#include <cstdint>
#include <cstddef>

// Problem constants
#define BATCH 8
#define TSEQ  1024
#define DDIM  384
#define DLANG 768
#define HID   512

#define NB   128      // one wave (<= 148 SMs), all blocks co-resident
#define NTHR 256
#define KSPLIT 4

// Scratch + barrier state (allocation-free rule: __device__ globals)
// Partial buffers: part[ks][b][j]  (ks-split GEMV partials; consumer sums)
__device__ float g_partA[KSPLIT * BATCH * HID];   // 16K floats
__device__ float g_partB[KSPLIT * BATCH * HID];
__device__ unsigned g_barrier[8];   // zeroed each launch via captured cudaMemsetAsync

// Dynamic smem layout:
//   float4 tile[6144]   : 98304 B (state tile: 64 rows x 96 float4)
//   float  sin[192]     :   768 B (input k-slice)
//   float4 spart[256]   :  4096 B (8 warps x 32 col-groups)
//   float4 fsh[96]      :  1536 B (f row)
//   uint64 mbar         :    16 B
#define TILE_F4 6144
#define SMEM_BYTES (TILE_F4 * 16 + 192 * 4 + 256 * 16 + 96 * 16 + 16)

extern __shared__ float4 smem_dyn[];

__device__ __forceinline__ uint32_t smem_u32(const void* p) {
    return (uint32_t)__cvta_generic_to_shared(p);
}

// ---------------------------------------------------------------------------
// Grid barrier (all NB blocks): single-lane atomicAdd + L2 spin.
// ---------------------------------------------------------------------------
__device__ __forceinline__ void grid_barrier(int phase) {
    __syncthreads();
    if (threadIdx.x == 0) {
        __threadfence();
        atomicAdd(&g_barrier[phase], 1u);
        volatile unsigned* p = &g_barrier[phase];
        while (*p < NB) { __nanosleep(16); }
        __threadfence();
    }
    __syncthreads();
}

// ---------------------------------------------------------------------------
// One K-split GEMV stage across all 128 blocks.
//   block -> (ks, b, jt):  ks = blockIdx.x>>5,  idx = blockIdx.x&31
//   active if idx < 8*JT;  b = idx/JT; jt = idx%JT (tile of 128 columns)
//   partial_out[ks][b][j] = sum_{i in ks-slice} in[b,i] * W[i,j]  (+bias if ks==0)
// Input: FIRST -> dense vector [B][K]; else -> partials [KSPLIT][B][K] summed
// in fixed order (deterministic).
// ---------------------------------------------------------------------------
template <int K, int N, int JT, bool FIRST>
__device__ __forceinline__ void chain_stage(const float* __restrict__ in,
                                            const float* __restrict__ W,
                                            const float* __restrict__ bias,
                                            float* __restrict__ out_part,
                                            float* sin, float4* spart) {
    constexpr int K4 = K / KSPLIT;     // k per split (192 or 128)
    constexpr int KW = K4 / 8;         // k per warp (24 or 16)
    const int ks  = blockIdx.x >> 5;
    const int idx = blockIdx.x & 31;
    if (idx < 8 * JT) {
        const int b  = idx / JT;
        const int jt = idx % JT;

        // ---- assemble this block's input k-slice into smem ----
        if (FIRST) {
            if (threadIdx.x < K4)
                sin[threadIdx.x] = in[(size_t)b * K + ks * K4 + threadIdx.x];
        } else {
            if (threadIdx.x < K4) {
                const size_t o = (size_t)b * K + ks * K4 + threadIdx.x;
                float s = in[o];                              // p = 0
                s += in[(size_t)(1 * BATCH) * K + o];
                s += in[(size_t)(2 * BATCH) * K + o];
                s += in[(size_t)(3 * BATCH) * K + o];
                sin[threadIdx.x] = s;
            }
        }
        __syncthreads();

        // ---- compute: warp = k-subslice, thread = float4 column group ----
        const int w  = threadIdx.x >> 5;
        const int j4 = threadIdx.x & 31;
        constexpr int NC4 = N / 4;
        const float4* Wp = (const float4*)W
                         + (size_t)(ks * K4 + w * KW) * NC4 + jt * 32 + j4;
        const float* sp = sin + w * KW;
        float4 acc = {0.f, 0.f, 0.f, 0.f};
#pragma unroll
        for (int i = 0; i < KW; ++i) {
            const float s = sp[i];
            const float4 wv = Wp[(size_t)i * NC4];
            acc.x += s * wv.x; acc.y += s * wv.y;
            acc.z += s * wv.z; acc.w += s * wv.w;
        }
        spart[w * 32 + j4] = acc;
        __syncthreads();

        // ---- reduce 8 warps, write partial ----
        if (threadIdx.x < 32) {
            float4 s = spart[threadIdx.x];
#pragma unroll
            for (int k = 1; k < 8; ++k) {
                const float4 v = spart[k * 32 + threadIdx.x];
                s.x += v.x; s.y += v.y; s.z += v.z; s.w += v.w;
            }
            if (ks == 0) {
                const float4 bb = ((const float4*)bias)[jt * 32 + threadIdx.x];
                s.x += bb.x; s.y += bb.y; s.z += bb.z; s.w += bb.w;
            }
            ((float4*)(out_part + (size_t)(ks * BATCH + b) * N))
                [jt * 32 + threadIdx.x] = s;
        }
    }
    // sin/spart reuse by the next stage is protected by grid_barrier's syncs.
}

// ---------------------------------------------------------------------------
// Fused kernel.
//
// Math note: language is broadcast along T, so k/v are identical for all key
// positions; softmax over a constant row is exactly uniform 1/T and ctx == v.
// The Q path and the T x T attention cancel analytically:
//   f[b] = (((language[b] Wv + bv) Wv2 + bv2) Wo + bo) Wout + bout
//   out[b,t,:] = state[b,t,:] + f[b,:]
//
// Overlap: one cp.async.bulk per block streams the 96KB state tile on the TMA
// pipe during the entire GEMV chain; all 128 blocks cooperate on every stage
// (K-split partials, consumer-side deterministic reduction).
// ---------------------------------------------------------------------------
__global__ void __launch_bounds__(NTHR, 1)
fused_cma_kernel(const float* __restrict__ state,
                 const float* __restrict__ language,
                 const float* __restrict__ Wv,  const float* __restrict__ bv,
                 const float* __restrict__ Wv2, const float* __restrict__ bv2,
                 const float* __restrict__ Wo,  const float* __restrict__ bo,
                 const float* __restrict__ Wout,const float* __restrict__ bout,
                 float* __restrict__ out) {
    float4*   tile  = smem_dyn;                              // 6144 float4
    float*    sin   = (float*)(smem_dyn + TILE_F4);          // 192 floats
    float4*   spart = (float4*)(sin + 192);                  // 256 float4
    float4*   fsh   = spart + 256;                           // 96 float4
    uint64_t* mbar  = (uint64_t*)(fsh + 96);

    // ---- Issue state-tile bulk copy first (TMA pipe; overlaps the chain) ----
    const int bres = blockIdx.x >> 4;                        // batch
    const int t0   = (blockIdx.x & 15) * 64;                 // row start
    const size_t base = ((size_t)bres * TSEQ + t0) * DDIM;

    const uint32_t mbar_s = smem_u32(mbar);
    const uint32_t tile_s = smem_u32(tile);
    if (threadIdx.x == 0) {
        asm volatile("mbarrier.init.shared.b64 [%0], 1;" :: "r"(mbar_s) : "memory");
        asm volatile("fence.proxy.async.shared::cta;" ::: "memory");
        asm volatile("mbarrier.arrive.expect_tx.shared.b64 _, [%0], %1;"
                     :: "r"(mbar_s), "r"((unsigned)(TILE_F4 * 16)) : "memory");
        asm volatile(
            "cp.async.bulk.shared::cta.global.mbarrier::complete_tx::bytes "
            "[%0], [%1], %2, [%3];"
            :: "r"(tile_s), "l"(state + base), "r"((unsigned)(TILE_F4 * 16)),
               "r"(mbar_s) : "memory");
    }

    // ---- GEMV chain: 4 stages, all blocks, K-split partials ----
    chain_stage<DLANG, HID, 4, true >(language, Wv,   bv,   g_partA, sin, spart);
    grid_barrier(0);
    chain_stage<HID,   HID, 4, false>(g_partA,  Wv2,  bv2,  g_partB, sin, spart);
    grid_barrier(1);
    chain_stage<HID,   HID, 4, false>(g_partB,  Wo,   bo,   g_partA, sin, spart);
    grid_barrier(2);
    chain_stage<HID,  DDIM, 3, false>(g_partA,  Wout, bout, g_partB, sin, spart);
    grid_barrier(3);

    // ---- Assemble f row for this block's batch (deterministic sum) ----
    if (threadIdx.x < DDIM / 4) {
        const float4* p0 = (const float4*)(g_partB + (size_t)(0 * BATCH + bres) * DDIM);
        const float4* p1 = (const float4*)(g_partB + (size_t)(1 * BATCH + bres) * DDIM);
        const float4* p2 = (const float4*)(g_partB + (size_t)(2 * BATCH + bres) * DDIM);
        const float4* p3 = (const float4*)(g_partB + (size_t)(3 * BATCH + bres) * DDIM);
        float4 a = p0[threadIdx.x], b = p1[threadIdx.x];
        float4 c = p2[threadIdx.x], d = p3[threadIdx.x];
        a.x += b.x; a.y += b.y; a.z += b.z; a.w += b.w;
        c.x += d.x; c.y += d.y; c.z += d.z; c.w += d.w;
        a.x += c.x; a.y += c.y; a.z += c.z; a.w += c.w;
        fsh[threadIdx.x] = a;
    }
    __syncthreads();

    // Register-resident f values: the dq sequence (stride 64 mod 96) has
    // period 3, so each thread touches only 3 distinct f float4s.
    const int dq0 = threadIdx.x % (DDIM / 4);
    const int dq1 = (dq0 + 64) % (DDIM / 4);
    const int dq2 = (dq0 + 32) % (DDIM / 4);
    const float4 f0 = fsh[dq0], f1 = fsh[dq1], f2 = fsh[dq2];

    // ---- Wait for the state tile (mbarrier parity 0, acquire) ----
    {
        uint32_t done;
        asm volatile(
            "{\n\t.reg .pred p;\n\t"
            "mbarrier.try_wait.parity.acquire.cta.shared::cta.b64 p, [%1], 0;\n\t"
            "selp.b32 %0, 1, 0, p;\n\t}"
            : "=r"(done) : "r"(mbar_s) : "memory");
        if (!done) {
            asm volatile(
                "{\n\t.reg .pred P1;\n\t"
                "WL_%=:\n\t"
                "mbarrier.try_wait.parity.acquire.cta.shared::cta.b64 P1, [%0], 0, 0x989680;\n\t"
                "@P1 bra.uni WD_%=;\n\t"
                "bra.uni WL_%=;\n\t"
                "WD_%=:\n\t}"
                :: "r"(mbar_s) : "memory");
        }
    }

    // ---- Residual add + store: 6144 float4 per block, 24 per thread ----
    float4* op = (float4*)(out + base);
#pragma unroll
    for (int it = 0; it < 24; ++it) {
        const int p = threadIdx.x + it * NTHR;
        float4 s = tile[p];
        const float4 fv = (it % 3 == 0) ? f0 : ((it % 3 == 1) ? f1 : f2);
        s.x += fv.x; s.y += fv.y; s.z += fv.z; s.w += fv.w;
        op[p] = s;
    }
}

// ---------------------------------------------------------------------------
// Inputs (metadata order):
//  0 state [B,T,D]   1 language [B,DL]
//  2 Wq 3 bq 4 Wk 5 bk 6 Wv 7 bv
//  8 Wq2 9 bq2 10 Wk2 11 bk2 12 Wv2 13 bv2
// 14 Wo 15 bo 16 Wout 17 bout
// Output: float32 [B,T,D]
// ---------------------------------------------------------------------------
extern "C" void kernel_launch(void* const* d_in, const int* in_sizes, int n_in,
                              void* d_out, int out_size) {
    (void)in_sizes; (void)n_in; (void)out_size;

    const float* state    = (const float*)d_in[0];
    const float* language = (const float*)d_in[1];
    const float* Wv   = (const float*)d_in[6];
    const float* bv   = (const float*)d_in[7];
    const float* Wv2  = (const float*)d_in[12];
    const float* bv2  = (const float*)d_in[13];
    const float* Wo   = (const float*)d_in[14];
    const float* bo   = (const float*)d_in[15];
    const float* Wout = (const float*)d_in[16];
    const float* bout = (const float*)d_in[17];
    float* out = (float*)d_out;

    cudaFuncSetAttribute(fused_cma_kernel,
                         cudaFuncAttributeMaxDynamicSharedMemorySize,
                         SMEM_BYTES);

    unsigned* barp = nullptr;
    cudaGetSymbolAddress((void**)&barp, g_barrier);

    // Reset barrier counters each launch (async memset is graph-capturable).
    cudaMemsetAsync(barp, 0, sizeof(g_barrier));

    fused_cma_kernel<<<NB, NTHR, SMEM_BYTES>>>(state, language,
                                               Wv, bv, Wv2, bv2, Wo, bo,
                                               Wout, bout, out);
}